// round 13
// baseline (speedup 1.0000x reference)
#include <cuda_runtime.h>
#include <cuda_bf16.h>
#include <math_constants.h>
#include <cstdint>

// Problem constants
#define Cc    256
#define HW    4096
#define NPTS  65536
#define KK    1024
#define NZQ   16777216
#define NBLK  512
#define BM    128
#define MARGIN 0.0125f

// Scratch (no device mallocs allowed)
__device__ float g_cnorm[KK];
__device__ float g_partial[NBLK];
__device__ int   g_idx[NPTS];
// codebook pre-packed to bf16, plain row-major [1024][256]
__device__ __align__(16) unsigned char g_cbh[KK * Cc * 2];

// ---------------------------------------------------------------------------
__device__ __forceinline__ uint32_t s2u(const void* p) {
    uint32_t a;
    asm("{ .reg .u64 t; cvta.to.shared.u64 t, %1; cvt.u32.u64 %0, t; }"
        : "=r"(a) : "l"(p));
    return a;
}
__device__ __forceinline__ uint32_t pk2(float a, float b) {
    __nv_bfloat162 h = __floats2bfloat162_rn(a, b);   // low = a, high = b
    return *(uint32_t*)&h;
}

// SMEM layout (dynamic, bytes). A/B rows padded to 528 B (33x16B) so that
// ldmatrix row addresses land on distinct banks within each 8-row phase.
#define A_STRIDE 528
#define D_STRIDE 129                 // floats; odd stride -> conflict-free scan
#define SM_CN   0                    // 4096   ||c||^2
#define SM_A    4096                 // 128*528 = 67584   z bf16 [m][c]
#define SM_B    (SM_A + 128*A_STRIDE)        // 71680, 67584   codes bf16 [k][c]
#define SM_D    (SM_B + 128*A_STRIDE)        // 139264, 128*129*4 = 66048
#define SM_M1   (SM_D + 128*D_STRIDE*4)      // 205312, 1024
#define SM_CNT  (SM_M1 + 1024)               // 206336, 1024
#define SM_CK   (SM_CNT + 1024)              // 207360, 4096  cand idx [128][2][8] u16
#define SM_CS   (SM_CK + 4096)               // 211456, 8192  cand s   [128][2][8] f32
#define SMEM_BYTES (SM_CS + 8192)            // 219648

// ---------------------------------------------------------------------------
// ||c_k||^2 — bitwise XLA order: sequential ascending c, non-FMA.
// ---------------------------------------------------------------------------
__global__ void cnorm_kernel(const float* __restrict__ cb) {
    int k = blockIdx.x * 256 + threadIdx.x;
    const float4* row = (const float4*)(cb + (size_t)k * Cc);
    float s = 0.f;
#pragma unroll
    for (int i = 0; i < Cc / 4; ++i) {
        float4 v = row[i];
        s = __fadd_rn(s, __fmul_rn(v.x, v.x));
        s = __fadd_rn(s, __fmul_rn(v.y, v.y));
        s = __fadd_rn(s, __fmul_rn(v.z, v.z));
        s = __fadd_rn(s, __fmul_rn(v.w, v.w));
    }
    g_cnorm[k] = s;
}

// ---------------------------------------------------------------------------
// Pack codebook to bf16 row-major [1024][256].
// ---------------------------------------------------------------------------
__global__ void cvt_kernel(const float* __restrict__ cb) {
    int t  = blockIdx.x * 256 + threadIdx.x;     // 128 x 256 = 32768
    int k  = t >> 5;
    int c0 = (t & 31) * 8;
    const float4* src = (const float4*)(cb + (size_t)k * Cc + c0);
    float4 a = src[0], b = src[1];
    uint4 v;
    v.x = pk2(a.x, a.y); v.y = pk2(a.z, a.w);
    v.z = pk2(b.x, b.y); v.w = pk2(b.z, b.w);
    *(uint4*)(g_cbh + ((size_t)k * Cc + c0) * 2) = v;
}

// ---------------------------------------------------------------------------
// Main: bf16 mma.sync coarse distances + margin candidates + exact fp32
// refine (refine replicates the reference's rounding chain bitwise).
// 8 warps = 2 m-halves (64 pts) x 4 k-quarters (32 codes); per warp
// 4x4 tiles of m16n8k16 -> 64x32 fp32 accumulators.
// ---------------------------------------------------------------------------
__global__ __launch_bounds__(256, 1)
void vq_main(const float* __restrict__ z, const float* __restrict__ cbf,
             float* __restrict__ out, int out_size)
{
    extern __shared__ char smem[];
    const int tid  = threadIdx.x;
    const int warp = tid >> 5;
    const int lane = tid & 31;

    float* cnp = (float*)(smem + SM_CN);
    for (int i = tid; i < KK; i += 256) cnp[i] = g_cnorm[i];

    const int n0  = blockIdx.x * BM;
    const int b   = n0 >> 12;
    const int hw0 = n0 & 4095;
    const float* zb = z + (size_t)b * Cc * HW + hw0;

    // ---- A tile: z -> bf16 [m][c], padded rows ----
    for (int p = warp; p < 128; p += 8) {
        int c0 = 2 * p;
#pragma unroll
        for (int j = 0; j < 4; ++j) {
            int m = lane + j * 32;
            float f0 = zb[(size_t)c0 * HW + m];
            float f1 = zb[(size_t)(c0 + 1) * HW + m];
            *(uint32_t*)(smem + SM_A + (size_t)m * A_STRIDE + c0 * 2) = pk2(f0, f1);
        }
    }
    // ---- B tile 0 ----
    {
        const uint4* s = (const uint4*)g_cbh;
        for (int i = tid; i < 4096; i += 256) {
            int r = i >> 5, c = i & 31;
            *(uint4*)(smem + SM_B + (size_t)r * A_STRIDE + c * 16) = s[r * 32 + c];
        }
    }
    __syncthreads();

    const uint32_t sb = s2u(smem);
    const int mh  = warp >> 2, kq = warp & 3;
    const int m0  = mh * 64,  nn0 = kq * 32;

    // ldmatrix row-base addresses (canonical idiom: r = lane%16, c = (lane/16)*8 elems)
    const uint32_t aRow = sb + SM_A + (uint32_t)(m0  + (lane & 15)) * A_STRIDE + (uint32_t)(lane >> 4) * 16;
    const uint32_t bRow = sb + SM_B + (uint32_t)(nn0 + (lane & 15)) * A_STRIDE + (uint32_t)(lane >> 4) * 16;

    // candidate state: this thread scans point (sm_pt), k-half (sh), all 8 tiles
    const int sm_pt = tid & 127, sh = tid >> 7;
    uint16_t* ckp = (uint16_t*)(smem + SM_CK) + ((size_t)sm_pt * 2 + sh) * 8;
    float*    csp = (float*)(smem + SM_CS) + ((size_t)sm_pt * 2 + sh) * 8;
    float m1 = CUDART_INF_F;
    int cnt = 0, ovf = 0;
    float* Ds = (float*)(smem + SM_D);

#define CAND_UPDATE(sv, kv) do {                                              \
        float _s = (sv);                                                      \
        if (_s < m1 + MARGIN) {                                               \
            if (cnt < 8) { ckp[cnt] = (uint16_t)(kv); csp[cnt] = _s; cnt++; } \
            else {                                                            \
                int w2 = 0;                                                   \
                for (int ii = 0; ii < 8; ++ii) {                              \
                    float si = csp[ii];                                       \
                    if (si < m1 + MARGIN) { uint16_t ki = ckp[ii];            \
                        ckp[w2] = ki; csp[w2] = si; w2++; }                   \
                }                                                             \
                cnt = w2;                                                     \
                if (cnt < 8) { ckp[cnt] = (uint16_t)(kv); csp[cnt] = _s; cnt++; } \
                else ovf = 1;                                                 \
            }                                                                 \
            if (_s < m1) m1 = _s;                                             \
        } } while (0)

    for (int nt = 0; nt < 8; ++nt) {
        float acc[4][4][4];
#pragma unroll
        for (int ti = 0; ti < 4; ++ti)
#pragma unroll
            for (int tj = 0; tj < 4; ++tj)
#pragma unroll
                for (int r = 0; r < 4; ++r) acc[ti][tj][r] = 0.f;

#pragma unroll 4
        for (int ks = 0; ks < 16; ++ks) {
            uint32_t a[4][4], bq[2][4];
#pragma unroll
            for (int ti = 0; ti < 4; ++ti) {
                uint32_t addr = aRow + (uint32_t)(ti * 16) * A_STRIDE + (uint32_t)ks * 32;
                asm volatile("ldmatrix.sync.aligned.m8n8.x4.shared.b16 {%0,%1,%2,%3}, [%4];"
                    : "=r"(a[ti][0]), "=r"(a[ti][1]), "=r"(a[ti][2]), "=r"(a[ti][3])
                    : "r"(addr));
            }
#pragma unroll
            for (int tp = 0; tp < 2; ++tp) {   // each x4 covers 2 n8 tiles
                uint32_t addr = bRow + (uint32_t)(tp * 16) * A_STRIDE + (uint32_t)ks * 32;
                asm volatile("ldmatrix.sync.aligned.m8n8.x4.shared.b16 {%0,%1,%2,%3}, [%4];"
                    : "=r"(bq[tp][0]), "=r"(bq[tp][1]), "=r"(bq[tp][2]), "=r"(bq[tp][3])
                    : "r"(addr));
            }
#pragma unroll
            for (int ti = 0; ti < 4; ++ti)
#pragma unroll
                for (int tj = 0; tj < 4; ++tj) {
                    uint32_t b0 = bq[tj >> 1][tj & 1];
                    uint32_t b1 = bq[tj >> 1][2 + (tj & 1)];
                    asm volatile(
                        "mma.sync.aligned.m16n8k16.row.col.f32.bf16.bf16.f32 "
                        "{%0,%1,%2,%3}, {%4,%5,%6,%7}, {%8,%9}, {%0,%1,%2,%3};"
                        : "+f"(acc[ti][tj][0]), "+f"(acc[ti][tj][1]),
                          "+f"(acc[ti][tj][2]), "+f"(acc[ti][tj][3])
                        : "r"(a[ti][0]), "r"(a[ti][1]), "r"(a[ti][2]), "r"(a[ti][3]),
                          "r"(b0), "r"(b1));
                }
        }
        __syncthreads();   // all warps done with B(nt); prev scans done

        // write dot products to D  (frag: d0/d1 row g cols 2t,2t+1; d2/d3 row g+8)
        {
            const int g = lane >> 2, tt = (lane & 3) * 2;
#pragma unroll
            for (int ti = 0; ti < 4; ++ti)
#pragma unroll
                for (int tj = 0; tj < 4; ++tj) {
                    float* d0 = Ds + (size_t)(m0 + ti * 16 + g) * D_STRIDE + nn0 + tj * 8 + tt;
                    d0[0] = acc[ti][tj][0];
                    d0[1] = acc[ti][tj][1];
                    float* d1 = d0 + 8 * D_STRIDE;
                    d1[0] = acc[ti][tj][2];
                    d1[1] = acc[ti][tj][3];
                }
        }
        // load B(nt+1) (overlaps with scan below after the sync)
        if (nt < 7) {
            const uint4* s = (const uint4*)(g_cbh + (size_t)(nt + 1) * 65536);
            for (int i = tid; i < 4096; i += 256) {
                int r = i >> 5, c = i & 31;
                *(uint4*)(smem + SM_B + (size_t)r * A_STRIDE + c * 16) = s[r * 32 + c];
            }
        }
        __syncthreads();   // D complete, B(nt+1) complete

        // scan D: coarse s = cn - 2*dot ; margin candidate tracking
        {
            const int kb = nt * 128 + sh * 64;
            const float* drow = Ds + (size_t)sm_pt * D_STRIDE + sh * 64;
            for (int j = 0; j < 64; ++j) {
                float s = fmaf(-2.f, drow[j], cnp[kb + j]);
                CAND_UPDATE(s, kb + j);
            }
        }
    }

    ((float*)(smem + SM_M1))[sm_pt * 2 + sh] = m1;
    ((int*)(smem + SM_CNT))[sm_pt * 2 + sh]  = ovf ? 255 : cnt;
    __syncthreads();

    // ---- exact refine (bitwise reference rounding chain) ----
    if (tid < BM) {
        const int m = tid;
        const float* m1p = (const float*)(smem + SM_M1);
        const int*   ctp = (const int*)(smem + SM_CNT);
        float g1 = fminf(m1p[m * 2], m1p[m * 2 + 1]);
        int c0n = ctp[m * 2], c1n = ctp[m * 2 + 1];
        const float* zrow = zb + m;
        int bi = 0;

        if (c0n == 255 || c1n == 255) {
            // overflow fallback: full exact scan (probability ~0)
            float zn = 0.f;
            for (int c = 0; c < Cc; ++c) {
                float v = zrow[(size_t)c * HW];
                zn = __fadd_rn(zn, __fmul_rn(v, v));
            }
            float bd = CUDART_INF_F;
            for (int k = 0; k < KK; ++k) {
                const float* cr = cbf + (size_t)k * Cc;
                float acc = 0.f;
                for (int c = 0; c < Cc; ++c)
                    acc = fmaf(zrow[(size_t)c * HW], cr[c], acc);
                float d = __fsub_rn(__fadd_rn(zn, cnp[k]), __fmul_rn(2.f, acc));
                if (d < bd) { bd = d; bi = k; }
            }
        } else {
            const uint16_t* k0p = (const uint16_t*)(smem + SM_CK) + (size_t)m * 16;
            const float*    s0p = (const float*)(smem + SM_CS) + (size_t)m * 16;
            int cand[16]; int nc = 0;
            for (int i = 0; i < c0n; ++i)
                if (s0p[i] < g1 + MARGIN) cand[nc++] = k0p[i];
            for (int i = 0; i < c1n; ++i)
                if (s0p[8 + i] < g1 + MARGIN) cand[nc++] = k0p[8 + i];
            if (nc <= 1) {
                bi = cand[0];
            } else {
                float zn = 0.f;
#pragma unroll 8
                for (int c = 0; c < Cc; ++c) {
                    float v = zrow[(size_t)c * HW];
                    zn = __fadd_rn(zn, __fmul_rn(v, v));
                }
                float bd = CUDART_INF_F; bi = 1 << 30;
                for (int i = 0; i < nc; ++i) {
                    int k = cand[i];
                    const float* cr = cbf + (size_t)k * Cc;
                    float acc = 0.f;
#pragma unroll 8
                    for (int c = 0; c < Cc; ++c)
                        acc = fmaf(zrow[(size_t)c * HW], cr[c], acc);
                    float d = __fsub_rn(__fadd_rn(zn, cnp[k]), __fmul_rn(2.f, acc));
                    if (d < bd || (d == bd && k < bi)) { bd = d; bi = k; }
                }
            }
        }
        g_idx[n0 + m] = bi;
        if (out_size >= NZQ + NPTS) out[NZQ + n0 + m] = (float)bi;
    }
}

// ---------------------------------------------------------------------------
// zq gather + straight-through output + loss partials (memory-bound)
// ---------------------------------------------------------------------------
__global__ __launch_bounds__(256) void outk(
    const float* __restrict__ z, const float* __restrict__ cb,
    float* __restrict__ out, int out_size)
{
    __shared__ int   idx_s[BM];
    __shared__ float wsum[8];
    const int tid  = threadIdx.x;
    const int warp = tid >> 5;
    const int lane = tid & 31;
    const int n0  = blockIdx.x * BM;
    const int b   = n0 >> 12;
    const int hw0 = n0 & 4095;
    const float* zb = z + (size_t)b * Cc * HW + hw0;
    float* outb = out + (size_t)b * Cc * HW + hw0;

    if (tid < BM) idx_s[tid] = g_idx[n0 + tid];
    __syncthreads();

    float lsum = 0.f;
    const bool wq = (out_size >= NZQ);
    for (int c = warp; c < Cc; c += 8) {
#pragma unroll
        for (int j = 0; j < 4; ++j) {
            int mm = lane + j * 32;
            float q  = cb[(size_t)idx_s[mm] * Cc + c];
            float zv = zb[(size_t)c * HW + mm];
            float df = __fsub_rn(q, zv);
            lsum = fmaf(df, df, lsum);
            if (wq) outb[(size_t)c * HW + mm] = __fadd_rn(zv, df);
        }
    }
#pragma unroll
    for (int o = 16; o > 0; o >>= 1)
        lsum += __shfl_down_sync(0xffffffffu, lsum, o);
    if (lane == 0) wsum[warp] = lsum;
    __syncthreads();
    if (tid == 0) {
        float s = 0.f;
#pragma unroll
        for (int w = 0; w < 8; ++w) s += wsum[w];
        g_partial[blockIdx.x] = s;
    }
}

// ---------------------------------------------------------------------------
// Deterministic loss finalize (tree reduce): loss = 0.75 * mean((zq - z)^2)
// ---------------------------------------------------------------------------
__global__ void fin_kernel(float* __restrict__ out, int out_size) {
    __shared__ float s[NBLK];
    int t = threadIdx.x;
    s[t] = g_partial[t];
    __syncthreads();
#pragma unroll
    for (int o = 256; o > 0; o >>= 1) {
        if (t < o) s[t] += s[t + o];
        __syncthreads();
    }
    if (t == 0 && out_size >= NZQ + NPTS + 1)
        out[NZQ + NPTS] = 0.75f * (s[0] * (1.0f / 16777216.0f));
}

// ---------------------------------------------------------------------------
extern "C" void kernel_launch(void* const* d_in, const int* in_sizes, int n_in,
                              void* d_out, int out_size) {
    const float* z  = (const float*)d_in[0];   // [16,256,64,64]
    const float* cb = (const float*)d_in[1];   // [1024,256]
    float* out = (float*)d_out;

    cudaFuncSetAttribute(vq_main, cudaFuncAttributeMaxDynamicSharedMemorySize,
                         SMEM_BYTES);

    cnorm_kernel<<<4, 256>>>(cb);
    cvt_kernel<<<128, 256>>>(cb);
    vq_main<<<NBLK, 256, SMEM_BYTES>>>(z, cb, out, out_size);
    outk<<<NBLK, 256>>>(z, cb, out, out_size);
    fin_kernel<<<1, NBLK>>>(out, out_size);
}